// round 5
// baseline (speedup 1.0000x reference)
#include <cuda_runtime.h>
#include <cstdint>

#define Bsz 16
#define Cin 128
#define Hh 64
#define Ww 64
#define HW 4096
#define Oc 256
#define ROWLEN 1152
#define ADIM 1161
#define TBL 1024
#define Rr 2.5f
#define Uu 0.83f
#define CONV_ELEMS 16777216LL
#define QMAX 32512.0f

// ---------------------------------------------------------------------------
__device__ int g_bucket[Oc];
__device__ int g_count[TBL];
__device__ int g_active[Oc];
__device__ int g_maskA[Oc];
__device__ int g_nactive;
__device__ unsigned g_maxin_bits;
__device__ unsigned g_maxw_bits;
__device__ float g_T[Bsz * 9 * HW];
__device__ int8_t g_A1[9 * 256 * 128];              // weight hi limb [k][m][c]
__device__ int8_t g_A0[9 * 256 * 128];              // weight lo limb
__device__ int8_t g_B1[(size_t)Bsz * HW * Cin];     // input hi limb NHWC
__device__ int8_t g_B0[(size_t)Bsz * HW * Cin];     // input lo limb

// ---------------------------------------------------------------------------
__device__ __forceinline__ void cp_async16(uint32_t dst, const void* src, bool valid) {
    int sz = valid ? 16 : 0;
    asm volatile("cp.async.cg.shared.global [%0], [%1], 16, %2;" :: "r"(dst), "l"(src), "r"(sz) : "memory");
}
#define CP_COMMIT() asm volatile("cp.async.commit_group;" ::: "memory")
#define CP_WAIT(n) asm volatile("cp.async.wait_group %0;" :: "n"(n) : "memory")

__device__ __forceinline__ uint32_t smem_u32(const void* p) {
    uint32_t a;
    asm("{ .reg .u64 t; cvta.to.shared.u64 t, %1; cvt.u32.u64 %0, t; }" : "=r"(a) : "l"(p));
    return a;
}

#define IMMA16832(d, a, b0_, b1_) \
    asm volatile("mma.sync.aligned.m16n8k32.row.col.s32.s8.s8.s32 " \
        "{%0,%1,%2,%3}, {%4,%5,%6,%7}, {%8,%9}, {%0,%1,%2,%3};" \
        : "+r"((d)[0]), "+r"((d)[1]), "+r"((d)[2]), "+r"((d)[3]) \
        : "r"((a)[0]), "r"((a)[1]), "r"((a)[2]), "r"((a)[3]), "r"(b0_), "r"(b1_))

// ---------------------------------------------------------------------------
__global__ void hash_kernels_kernel(const float* __restrict__ kern,
                                    const float* __restrict__ a,
                                    const float* __restrict__ bptr) {
    __shared__ __align__(16) float a_s[ADIM + 3];
    __shared__ float sred[256];
    int o = threadIdx.x;
    for (int i = o; i < ADIM; i += 256) a_s[i] = a[i];
    for (int i = o; i < TBL; i += 256) g_count[i] = 0;
    if (o == 0) { g_maxin_bits = 0u; g_maxw_bits = 0u; }
    __syncthreads();
    const float4* row = reinterpret_cast<const float4*>(kern + (size_t)o * ROWLEN);
    const float4* a4 = reinterpret_cast<const float4*>(a_s);
    float s = 0.f, d = 0.f;
    for (int j = 0; j < ROWLEN / 4; j++) {
        float4 kv = row[j], av = a4[j];
        s += kv.x * kv.x + kv.y * kv.y + kv.z * kv.z + kv.w * kv.w;
        d += kv.x * av.x + kv.y * av.y + kv.z * av.z + kv.w * av.w;
    }
    sred[o] = s;
    __syncthreads();
    for (int st = 128; st > 0; st >>= 1) {
        if (o < st) sred[o] = fmaxf(sred[o], sred[o + st]);
        __syncthreads();
    }
    float scale = Uu / sqrtf(sred[0]);
    float dot = scale * d;
    float p = scale * scale * s;
    float acc = 0.f, t = p;
#pragma unroll
    for (int i = 0; i < 9; i++) { acc += t * a_s[ROWLEN + i]; t = t * t; }
    int hi = (int)floorf((dot + acc + bptr[0]) / Rr);
    int bkt = hi % TBL;
    if (bkt < 0) bkt = -bkt;
    g_bucket[o] = bkt;
}

// ---------------------------------------------------------------------------
// voteA: 9-channel 1x1 reduction + fused |input| max
// ---------------------------------------------------------------------------
__global__ void voteA_kernel(const float* __restrict__ in, const float* __restrict__ a) {
    __shared__ __align__(16) float w_s[Cin * 12];
    int tid = threadIdx.x;
    for (int i = tid; i < ROWLEN; i += 256) { int c = i / 9, k = i % 9; w_s[c * 12 + k] = a[i]; }
    __syncthreads();
    int b = blockIdx.y;
    int p = blockIdx.x * 256 + tid;
    const float* ip = in + (size_t)b * Cin * HW + p;
    float acc[9];
#pragma unroll
    for (int k = 0; k < 9; k++) acc[k] = 0.f;
    float mx = 0.f;
#pragma unroll 8
    for (int c = 0; c < Cin; c++) {
        float v = ip[(size_t)c * HW];
        mx = fmaxf(mx, fabsf(v));
        float4 w0 = *reinterpret_cast<const float4*>(&w_s[c * 12]);
        float4 w1 = *reinterpret_cast<const float4*>(&w_s[c * 12 + 4]);
        float w8 = w_s[c * 12 + 8];
        acc[0] += v * w0.x; acc[1] += v * w0.y; acc[2] += v * w0.z; acc[3] += v * w0.w;
        acc[4] += v * w1.x; acc[5] += v * w1.y; acc[6] += v * w1.z; acc[7] += v * w1.w;
        acc[8] += v * w8;
    }
    float* tp = g_T + (size_t)b * 9 * HW + p;
#pragma unroll
    for (int k = 0; k < 9; k++) tp[k * HW] = acc[k];
#pragma unroll
    for (int o = 16; o > 0; o >>= 1) mx = fmaxf(mx, __shfl_xor_sync(0xffffffff, mx, o));
    if ((tid & 31) == 0) atomicMax(&g_maxin_bits, __float_as_uint(mx));
}

__global__ void voteB_kernel(const float* __restrict__ a, const float* __restrict__ bptr) {
    __shared__ int hist[TBL];
    __shared__ float ae[9];
    int tid = threadIdx.x;
    for (int i = tid; i < TBL; i += 256) hist[i] = 0;
    if (tid < 9) ae[tid] = a[ROWLEN + tid];
    __syncthreads();
    int b = blockIdx.y;
    int p = blockIdx.x * 256 + tid;
    int y = p >> 6, x = p & 63;
    const float* tb = g_T + (size_t)b * 9 * HW;
    float s = 0.f;
#pragma unroll
    for (int dy = 0; dy < 3; dy++) {
        int gy = y + dy - 1;
        if (gy < 0 || gy >= Hh) continue;
#pragma unroll
        for (int dx = 0; dx < 3; dx++) {
            int gx = x + dx - 1;
            if (gx < 0 || gx >= Ww) continue;
            int k = dy * 3 + dx;
            s += tb[k * HW + gy * Ww + gx] + 0.5f * ae[k];
        }
    }
    int vi = (int)floorf((s + bptr[0]) / Rr);
    int vb = vi % TBL;
    if (vb < 0) vb = -vb;
    atomicAdd(&hist[vb], 1);
    __syncthreads();
    for (int i = tid; i < TBL; i += 256) {
        int c = hist[i];
        if (c) atomicAdd(&g_count[i], c);
    }
}

// ---------------------------------------------------------------------------
__global__ void argmax_mask_kernel(float* __restrict__ out, long long out_size) {
    __shared__ int sval[TBL];
    __shared__ int sidx[TBL];
    int t = threadIdx.x;
    sval[t] = g_count[t];
    sidx[t] = t;
    __syncthreads();
    for (int s = TBL / 2; s > 0; s >>= 1) {
        if (t < s) {
            int v2 = sval[t + s], i2 = sidx[t + s];
            if (v2 > sval[t] || (v2 == sval[t] && i2 < sidx[t])) { sval[t] = v2; sidx[t] = i2; }
        }
        __syncthreads();
    }
    int winner = sidx[0];
    if (t == 0) g_nactive = 0;
    __syncthreads();
    if (t < Oc) {
        int m = (g_bucket[t] == winner) ? 1 : 0;
        g_maskA[t] = m;
        if (m) { int pos = atomicAdd(&g_nactive, 1); g_active[pos] = t; }
        if (out_size >= CONV_ELEMS + 1 + Oc) out[CONV_ELEMS + 1 + t] = m ? 1.f : 0.f;
    }
    if (t == 0 && out_size >= CONV_ELEMS + 1) out[CONV_ELEMS] = (float)winner;
}

// ---------------------------------------------------------------------------
// Zero only INACTIVE output planes (conv fully overwrites active planes).
// grid = Bsz*Oc blocks, 256 threads; 4096 floats = 1024 float4.
// ---------------------------------------------------------------------------
__global__ void zero_planes_kernel(float* __restrict__ out) {
    int plane = blockIdx.x;
    int oc = plane & 255;
    if (g_maskA[oc]) return;
    float4* p = reinterpret_cast<float4*>(out + (size_t)plane * HW);
    float4 z = make_float4(0.f, 0.f, 0.f, 0.f);
    int t = threadIdx.x;
#pragma unroll
    for (int i = 0; i < 4; i++) p[t + i * 256] = z;
}

// ---------------------------------------------------------------------------
__global__ void maxw_kernel(const float* __restrict__ kern) {
    int idx = blockIdx.x * 256 + threadIdx.x;
    float m = 0.f;
    for (int i = idx; i < Oc * ROWLEN; i += 256 * 256) m = fmaxf(m, fabsf(kern[i]));
#pragma unroll
    for (int o = 16; o > 0; o >>= 1) m = fmaxf(m, __shfl_xor_sync(0xffffffff, m, o));
    if ((threadIdx.x & 31) == 0) atomicMax(&g_maxw_bits, __float_as_uint(m));
}

// ---------------------------------------------------------------------------
// prepA: active-kernel weights -> [k][m][c] int8 limbs (m >= nact zeroed)
// ---------------------------------------------------------------------------
__global__ void prepA_kernel(const float* __restrict__ kern) {
    int idx = blockIdx.x * 256 + threadIdx.x;  // (k*256+m)*128+c
    int c = idx & 127;
    int m = (idx >> 7) & 255;
    int k = idx >> 15;
    int nact = g_nactive;
    float v = 0.f;
    if (m < nact) {
        int oc = g_active[m];
        v = kern[(size_t)oc * ROWLEN + c * 9 + k];
    }
    float inv = QMAX / __uint_as_float(g_maxw_bits);
    int q = __float2int_rn(v * inv);
    int a1 = (q + 128) >> 8;
    int a0 = q - (a1 << 8);
    g_A1[idx] = (int8_t)a1;
    g_A0[idx] = (int8_t)a0;
}

// ---------------------------------------------------------------------------
// prepB: NCHW -> NHWC int8 limbs
// ---------------------------------------------------------------------------
__global__ void prepB_kernel(const float* __restrict__ in) {
    __shared__ float s[128 * 33];
    int tid = threadIdx.x;
    int g = blockIdx.x * 32;
    int b = g >> 12;
    int px0 = g & 4095;
    const float* ib = in + (size_t)b * Cin * HW + px0;
    for (int i = tid; i < 32 * 128; i += 256) {
        int c = i >> 5, p = i & 31;
        s[c * 33 + p] = ib[(size_t)c * HW + p];
    }
    __syncthreads();
    float inv = QMAX / __uint_as_float(g_maxin_bits);
    for (int i = tid; i < 32 * 32; i += 256) {
        int p = i >> 5, cg = i & 31;
        char4 h, l;
        int c = cg * 4;
#pragma unroll
        for (int j = 0; j < 4; j++) {
            float v = s[(c + j) * 33 + p];
            int q = __float2int_rn(v * inv);
            int a1 = (q + 128) >> 8;
            int a0 = q - (a1 << 8);
            ((int8_t*)&h)[j] = (int8_t)a1;
            ((int8_t*)&l)[j] = (int8_t)a0;
        }
        size_t o = ((size_t)(g + p) * 128 + c) >> 2;
        reinterpret_cast<char4*>(g_B1)[o] = h;
        reinterpret_cast<char4*>(g_B0)[o] = l;
    }
}

// ---------------------------------------------------------------------------
// Main conv: 9 shifted GEMMs via IMMA m16n8k32 (asymmetric 2-limb int8).
// CTA tile: M=128 px x N=128 ocs; 8 warps 2(M)x4(N), warp tile 64px x 32oc.
// 18 steps (k-shift x 64-c half), double-buffered weights; patch loaded once.
// ---------------------------------------------------------------------------
#define PSTRI 176
#define SM_P1 0
#define SM_P0 46464
#define SM_W 92928
#define WBUFSZ 20480
#define SM_ACT 133888
#define SM_TOT 134400

__global__ void __launch_bounds__(256, 1)
conv_mma_kernel(float* __restrict__ out) {
    extern __shared__ char smem[];
    const int tid = threadIdx.x;
    const int lane = tid & 31;
    const int wid = tid >> 5;
    const int nact = g_nactive;
    const int n0 = blockIdx.y << 7;
    if (n0 >= nact) return;

    const int pxg = blockIdx.x << 7;
    const int bb = pxg >> 12;
    const int y0 = (pxg & 4095) >> 6;

    uint32_t sb = smem_u32(smem);

    if (tid < 128) {
        int nn = n0 + tid;
        ((int*)(smem + SM_ACT))[tid] = (nn < nact) ? g_active[nn] : -1;
    }

    // patch: 264 px-rows x 8 chunks x 2 limbs
    for (int i = tid; i < 4224; i += 256) {
        int limb = (i >= 2112) ? 1 : 0;
        int j = i - limb * 2112;
        int row = j >> 3, ch = j & 7;
        int pr = row / 66, pc = row - pr * 66;
        int gy = y0 - 1 + pr, gx = pc - 1;
        bool v = ((unsigned)gy < 64u) && ((unsigned)gx < 64u);
        const int8_t* base = limb ? g_B0 : g_B1;
        const int8_t* src = v ? base + (((size_t)(bb << 12) + gy * 64 + gx) * 128 + ch * 16) : base;
        cp_async16(sb + (limb ? SM_P0 : SM_P1) + row * PSTRI + ch * 16, src, v);
    }
    // weights step 0
    for (int i = tid; i < 1024; i += 256) {
        int limb = i >> 9;
        int j = i & 511;
        int row = j >> 2, c16 = j & 3;
        const int8_t* base = limb ? g_A0 : g_A1;
        const int8_t* src = base + ((size_t)(n0 + row) * 128 + c16 * 16);
        cp_async16(sb + SM_W + limb * 10240 + row * 80 + c16 * 16, src, true);
    }
    CP_COMMIT();

    int acc11[4][4][4];
    int accM[4][4][4];
#pragma unroll
    for (int a = 0; a < 4; a++)
#pragma unroll
        for (int b2 = 0; b2 < 4; b2++)
#pragma unroll
            for (int c = 0; c < 4; c++) { acc11[a][b2][c] = 0; accM[a][b2][c] = 0; }

    const int pxbase = (wid & 1) << 6;
    const int nbase = (wid >> 1) << 5;
    const int q4 = (lane & 3) << 2;
    const int rr = lane >> 2;

    for (int s = 0; s < 18; s++) {
        if (s < 17) {
            int s1 = s + 1;
            int k1 = s1 >> 1, ch1 = s1 & 1;
            for (int i = tid; i < 1024; i += 256) {
                int limb = i >> 9;
                int j = i & 511;
                int row = j >> 2, c16 = j & 3;
                const int8_t* base = limb ? g_A0 : g_A1;
                const int8_t* src = base + ((size_t)(k1 * 256 + n0 + row) * 128 + ch1 * 64 + c16 * 16);
                cp_async16(sb + SM_W + (s1 & 1) * WBUFSZ + limb * 10240 + row * 80 + c16 * 16, src, true);
            }
            CP_COMMIT();
            CP_WAIT(1);
        } else {
            CP_WAIT(0);
        }
        __syncthreads();

        const int k = s >> 1, chalf = s & 1;
        const int dy = k / 3, dx = k - dy * 3;
        const char* WH = smem + SM_W + (s & 1) * WBUFSZ;
        const char* WL = WH + 10240;

        int aoff[4];
#pragma unroll
        for (int mf = 0; mf < 4; mf++) {
            int px = pxbase + mf * 16 + rr;
            int prow = ((px >> 6) + dy) * 66 + (px & 63) + dx;
            aoff[mf] = prow * PSTRI + chalf * 64 + q4;
        }

#pragma unroll
        for (int cs = 0; cs < 2; cs++) {
            const int cb = cs * 32;
            uint32_t a1f[4][4], a0f[4][4];
#pragma unroll
            for (int mf = 0; mf < 4; mf++) {
                int o = aoff[mf] + cb;
                a1f[mf][0] = *(const uint32_t*)(smem + SM_P1 + o);
                a1f[mf][1] = *(const uint32_t*)(smem + SM_P1 + o + 8 * PSTRI);
                a1f[mf][2] = *(const uint32_t*)(smem + SM_P1 + o + 16);
                a1f[mf][3] = *(const uint32_t*)(smem + SM_P1 + o + 8 * PSTRI + 16);
                a0f[mf][0] = *(const uint32_t*)(smem + SM_P0 + o);
                a0f[mf][1] = *(const uint32_t*)(smem + SM_P0 + o + 8 * PSTRI);
                a0f[mf][2] = *(const uint32_t*)(smem + SM_P0 + o + 16);
                a0f[mf][3] = *(const uint32_t*)(smem + SM_P0 + o + 8 * PSTRI + 16);
            }
#pragma unroll
            for (int nf = 0; nf < 4; nf++) {
                int bo = (nbase + nf * 8 + rr) * 80 + cb + q4;
                uint32_t bh0 = *(const uint32_t*)(WH + bo);
                uint32_t bh1 = *(const uint32_t*)(WH + bo + 16);
                uint32_t bl0 = *(const uint32_t*)(WL + bo);
                uint32_t bl1 = *(const uint32_t*)(WL + bo + 16);
#pragma unroll
                for (int mf = 0; mf < 4; mf++) {
                    IMMA16832(acc11[mf][nf], a1f[mf], bh0, bh1);
                    IMMA16832(accM[mf][nf], a1f[mf], bl0, bl1);
                    IMMA16832(accM[mf][nf], a0f[mf], bh0, bh1);
                }
            }
        }
        __syncthreads();
    }

    // epilogue
    float s2 = __uint_as_float(g_maxin_bits) * __uint_as_float(g_maxw_bits) *
               (1.0f / (QMAX * QMAX));
    const int* act = (const int*)(smem + SM_ACT);
#pragma unroll
    for (int mf = 0; mf < 4; mf++) {
#pragma unroll
        for (int nf = 0; nf < 4; nf++) {
            int col = nbase + nf * 8 + (lane & 3) * 2;
            int oc0 = act[col];
            int oc1 = act[col + 1];
#pragma unroll
            for (int h = 0; h < 2; h++) {
                int row = pxbase + mf * 16 + rr + h * 8;
                int y = y0 + (row >> 6);
                int x = row & 63;
                size_t pixoff = (size_t)y * 64 + x;
                float v0 = fmaf(65536.f, (float)acc11[mf][nf][h * 2 + 0],
                                256.f * (float)accM[mf][nf][h * 2 + 0]) * s2;
                float v1 = fmaf(65536.f, (float)acc11[mf][nf][h * 2 + 1],
                                256.f * (float)accM[mf][nf][h * 2 + 1]) * s2;
                if (oc0 >= 0) out[(((size_t)bb * Oc + oc0) << 12) + pixoff] = v0;
                if (oc1 >= 0) out[(((size_t)bb * Oc + oc1) << 12) + pixoff] = v1;
            }
        }
    }
}

// ---------------------------------------------------------------------------
extern "C" void kernel_launch(void* const* d_in, const int* in_sizes, int n_in,
                              void* d_out, int out_size) {
    const float* inp = (const float*)d_in[0];
    const float* kern = (const float*)d_in[1];
    const float* a = (const float*)d_in[2];
    const float* b = (const float*)d_in[3];
    float* out = (float*)d_out;

    cudaFuncSetAttribute(conv_mma_kernel, cudaFuncAttributeMaxDynamicSharedMemorySize, SM_TOT);

    hash_kernels_kernel<<<1, 256>>>(kern, a, b);
    voteA_kernel<<<dim3(HW / 256, Bsz), 256>>>(inp, a);
    voteB_kernel<<<dim3(HW / 256, Bsz), 256>>>(a, b);
    argmax_mask_kernel<<<1, TBL>>>(out, (long long)out_size);
    zero_planes_kernel<<<Bsz * Oc, 256>>>(out);
    maxw_kernel<<<256, 256>>>(kern);
    prepA_kernel<<<1152, 256>>>(kern);
    prepB_kernel<<<2048, 256>>>(inp);
    conv_mma_kernel<<<dim3(512, 2), 256, SM_TOT>>>(out);
}

// round 6
// speedup vs baseline: 3.1145x; 3.1145x over previous
#include <cuda_runtime.h>
#include <cuda_fp16.h>
#include <cstdint>

#define Bsz 16
#define Cin 128
#define Hh 64
#define Ww 64
#define HW 4096
#define Oc 256
#define ROWLEN 1152
#define ADIM 1161
#define TBL 1024
#define Rr 2.5f
#define Uu 0.83f
#define CONV_ELEMS 16777216LL

// ---------------------------------------------------------------------------
__device__ int g_bucket[Oc];
__device__ int g_count[TBL];
__device__ int g_active[Oc];
__device__ int g_maskA[Oc];
__device__ int g_nactive;
__device__ float g_dotv[Oc];
__device__ float g_nrm[Oc];
__device__ float g_T[Bsz * 9 * HW];
__device__ __half g_Ah[9 * 256 * 128];             // weights [k][m][c] fp16
__device__ __half g_Bh[(size_t)Bsz * HW * Cin];    // input NHWC hi limb
__device__ __half g_Bl[(size_t)Bsz * HW * Cin];    // input NHWC lo limb

// ---------------------------------------------------------------------------
__device__ __forceinline__ void cp_async16(uint32_t dst, const void* src, bool valid) {
    int sz = valid ? 16 : 0;
    asm volatile("cp.async.cg.shared.global [%0], [%1], 16, %2;" :: "r"(dst), "l"(src), "r"(sz) : "memory");
}
#define CP_COMMIT() asm volatile("cp.async.commit_group;" ::: "memory")
#define CP_WAIT(n) asm volatile("cp.async.wait_group %0;" :: "n"(n) : "memory")

__device__ __forceinline__ uint32_t smem_u32(const void* p) {
    uint32_t a;
    asm("{ .reg .u64 t; cvta.to.shared.u64 t, %1; cvt.u32.u64 %0, t; }" : "=r"(a) : "l"(p));
    return a;
}

#define MMA16816F(d, a, b0_, b1_) \
    asm volatile("mma.sync.aligned.m16n8k16.row.col.f32.f16.f16.f32 " \
        "{%0,%1,%2,%3}, {%4,%5,%6,%7}, {%8,%9}, {%0,%1,%2,%3};" \
        : "+f"((d)[0]), "+f"((d)[1]), "+f"((d)[2]), "+f"((d)[3]) \
        : "r"((a)[0]), "r"((a)[1]), "r"((a)[2]), "r"((a)[3]), "r"(b0_), "r"(b1_))

// ---------------------------------------------------------------------------
// hashA: one warp per kernel row -> dot(row, a) and ||row||^2. 32 blocks.
// Also zeroes the vote histogram (32 entries per block).
// ---------------------------------------------------------------------------
__global__ void hashA_kernel(const float* __restrict__ kern,
                             const float* __restrict__ a) {
    int tid = threadIdx.x;
    int wid = tid >> 5, lane = tid & 31;
    if (tid < 32) g_count[blockIdx.x * 32 + tid] = 0;
    int row = blockIdx.x * 8 + wid;
    const float4* kr = reinterpret_cast<const float4*>(kern + (size_t)row * ROWLEN);
    const float4* a4 = reinterpret_cast<const float4*>(a);
    float s = 0.f, d = 0.f;
    for (int j = lane; j < ROWLEN / 4; j += 32) {
        float4 kv = kr[j], av = __ldg(&a4[j]);
        s += kv.x * kv.x + kv.y * kv.y + kv.z * kv.z + kv.w * kv.w;
        d += kv.x * av.x + kv.y * av.y + kv.z * av.z + kv.w * av.w;
    }
#pragma unroll
    for (int o = 16; o > 0; o >>= 1) {
        s += __shfl_xor_sync(0xffffffff, s, o);
        d += __shfl_xor_sync(0xffffffff, d, o);
    }
    if (lane == 0) { g_dotv[row] = d; g_nrm[row] = s; }
}

// ---------------------------------------------------------------------------
// hashB: finish ALSH hash per row (max-norm reduce + powers + bucket).
// ---------------------------------------------------------------------------
__global__ void hashB_kernel(const float* __restrict__ a,
                             const float* __restrict__ bptr) {
    __shared__ float sred[256];
    __shared__ float ae[9];
    int o = threadIdx.x;
    float s = g_nrm[o];
    sred[o] = s;
    if (o < 9) ae[o] = a[ROWLEN + o];
    __syncthreads();
    for (int st = 128; st > 0; st >>= 1) {
        if (o < st) sred[o] = fmaxf(sred[o], sred[o + st]);
        __syncthreads();
    }
    float scale = Uu / sqrtf(sred[0]);
    float dot = scale * g_dotv[o];
    float p = scale * scale * s;
    float acc = 0.f, t = p;
#pragma unroll
    for (int i = 0; i < 9; i++) { acc += t * ae[i]; t = t * t; }
    int hi = (int)floorf((dot + acc + bptr[0]) / Rr);
    int bkt = hi % TBL;
    if (bkt < 0) bkt = -bkt;
    g_bucket[o] = bkt;
}

// ---------------------------------------------------------------------------
__global__ void voteA_kernel(const float* __restrict__ in, const float* __restrict__ a) {
    __shared__ __align__(16) float w_s[Cin * 12];
    int tid = threadIdx.x;
    for (int i = tid; i < ROWLEN; i += 256) { int c = i / 9, k = i % 9; w_s[c * 12 + k] = a[i]; }
    __syncthreads();
    int b = blockIdx.y;
    int p = blockIdx.x * 256 + tid;
    const float* ip = in + (size_t)b * Cin * HW + p;
    float acc[9];
#pragma unroll
    for (int k = 0; k < 9; k++) acc[k] = 0.f;
#pragma unroll 8
    for (int c = 0; c < Cin; c++) {
        float v = ip[(size_t)c * HW];
        float4 w0 = *reinterpret_cast<const float4*>(&w_s[c * 12]);
        float4 w1 = *reinterpret_cast<const float4*>(&w_s[c * 12 + 4]);
        float w8 = w_s[c * 12 + 8];
        acc[0] += v * w0.x; acc[1] += v * w0.y; acc[2] += v * w0.z; acc[3] += v * w0.w;
        acc[4] += v * w1.x; acc[5] += v * w1.y; acc[6] += v * w1.z; acc[7] += v * w1.w;
        acc[8] += v * w8;
    }
    float* tp = g_T + (size_t)b * 9 * HW + p;
#pragma unroll
    for (int k = 0; k < 9; k++) tp[k * HW] = acc[k];
}

__global__ void voteB_kernel(const float* __restrict__ a, const float* __restrict__ bptr) {
    __shared__ int hist[TBL];
    __shared__ float ae[9];
    int tid = threadIdx.x;
    for (int i = tid; i < TBL; i += 256) hist[i] = 0;
    if (tid < 9) ae[tid] = a[ROWLEN + tid];
    __syncthreads();
    int b = blockIdx.y;
    int p = blockIdx.x * 256 + tid;
    int y = p >> 6, x = p & 63;
    const float* tb = g_T + (size_t)b * 9 * HW;
    float s = 0.f;
#pragma unroll
    for (int dy = 0; dy < 3; dy++) {
        int gy = y + dy - 1;
        if (gy < 0 || gy >= Hh) continue;
#pragma unroll
        for (int dx = 0; dx < 3; dx++) {
            int gx = x + dx - 1;
            if (gx < 0 || gx >= Ww) continue;
            int k = dy * 3 + dx;
            s += tb[k * HW + gy * Ww + gx] + 0.5f * ae[k];
        }
    }
    int vi = (int)floorf((s + bptr[0]) / Rr);
    int vb = vi % TBL;
    if (vb < 0) vb = -vb;
    atomicAdd(&hist[vb], 1);
    __syncthreads();
    for (int i = tid; i < TBL; i += 256) {
        int c = hist[i];
        if (c) atomicAdd(&g_count[i], c);
    }
}

// ---------------------------------------------------------------------------
__global__ void argmax_mask_kernel(float* __restrict__ out, long long out_size) {
    __shared__ int sval[TBL];
    __shared__ int sidx[TBL];
    int t = threadIdx.x;
    sval[t] = g_count[t];
    sidx[t] = t;
    __syncthreads();
    for (int s = TBL / 2; s > 0; s >>= 1) {
        if (t < s) {
            int v2 = sval[t + s], i2 = sidx[t + s];
            if (v2 > sval[t] || (v2 == sval[t] && i2 < sidx[t])) { sval[t] = v2; sidx[t] = i2; }
        }
        __syncthreads();
    }
    int winner = sidx[0];
    if (t == 0) g_nactive = 0;
    __syncthreads();
    if (t < Oc) {
        int m = (g_bucket[t] == winner) ? 1 : 0;
        g_maskA[t] = m;
        if (m) { int pos = atomicAdd(&g_nactive, 1); g_active[pos] = t; }
        if (out_size >= CONV_ELEMS + 1 + Oc) out[CONV_ELEMS + 1 + t] = m ? 1.f : 0.f;
    }
    if (t == 0 && out_size >= CONV_ELEMS + 1) out[CONV_ELEMS] = (float)winner;
}

// ---------------------------------------------------------------------------
__global__ void zero_planes_kernel(float* __restrict__ out) {
    int plane = blockIdx.x;
    int oc = plane & 255;
    if (g_maskA[oc]) return;
    float4* p = reinterpret_cast<float4*>(out + (size_t)plane * HW);
    float4 z = make_float4(0.f, 0.f, 0.f, 0.f);
    int t = threadIdx.x;
#pragma unroll
    for (int i = 0; i < 4; i++) p[t + i * 256] = z;
}

// ---------------------------------------------------------------------------
// prepA: active-kernel weights -> [k][m][c] single fp16 (m >= nact zeroed)
// ---------------------------------------------------------------------------
__global__ void prepA_kernel(const float* __restrict__ kern) {
    int idx = blockIdx.x * 256 + threadIdx.x;
    int c = idx & 127;
    int m = (idx >> 7) & 255;
    int k = idx >> 15;
    int nact = g_nactive;
    float v = 0.f;
    if (m < nact) {
        int oc = g_active[m];
        v = kern[(size_t)oc * ROWLEN + c * 9 + k];
    }
    g_Ah[idx] = __float2half_rn(v);
}

// ---------------------------------------------------------------------------
// prepB: NCHW -> NHWC, input split into two fp16 limbs.
// ---------------------------------------------------------------------------
__global__ void prepB_kernel(const float* __restrict__ in) {
    __shared__ float s[128 * 33];
    int tid = threadIdx.x;
    int g = blockIdx.x * 32;
    int b = g >> 12;
    int px0 = g & 4095;
    const float* ib = in + (size_t)b * Cin * HW + px0;
    for (int i = tid; i < 32 * 128; i += 256) {
        int c = i >> 5, p = i & 31;
        s[c * 33 + p] = ib[(size_t)c * HW + p];
    }
    __syncthreads();
    for (int i = tid; i < 32 * 64; i += 256) {
        int p = i >> 6, ch2 = i & 63;
        int c = ch2 * 2;
        float v0 = s[c * 33 + p];
        float v1 = s[(c + 1) * 33 + p];
        __half h0 = __float2half_rn(v0);
        __half h1 = __float2half_rn(v1);
        __half l0 = __float2half_rn(v0 - __half2float(h0));
        __half l1 = __float2half_rn(v1 - __half2float(h1));
        size_t o = ((size_t)(g + p) * 128 + c) >> 1;
        reinterpret_cast<__half2*>(g_Bh)[o] = __halves2half2(h0, h1);
        reinterpret_cast<__half2*>(g_Bl)[o] = __halves2half2(l0, l1);
    }
}

// ---------------------------------------------------------------------------
// Main conv: 9 shifted GEMMs, fp16 2-term (input hi/lo x weight single).
// CTA tile M=128 px x N=128 ocs; 8 warps 2(M)x4(N); 18 double-buffered steps.
// ---------------------------------------------------------------------------
#define PSTR 136
#define PROWB (PSTR * 2)
#define SM_PH 0
#define SM_PL 71808
#define SM_W 143616
#define WBUF 18432
#define WROWB 144
#define SM_ACT 180480
#define SM_TOT 180992

__global__ void __launch_bounds__(256, 1)
conv_mma_kernel(float* __restrict__ out) {
    extern __shared__ char smem[];
    const int tid = threadIdx.x;
    const int lane = tid & 31;
    const int wid = tid >> 5;
    const int nact = g_nactive;
    const int n0 = blockIdx.y << 7;
    if (n0 >= nact) return;

    const int pxg = blockIdx.x << 7;
    const int bb = pxg >> 12;
    const int y0 = (pxg & 4095) >> 6;

    uint32_t sb = smem_u32(smem);

    if (tid < 128) {
        int nn = n0 + tid;
        ((int*)(smem + SM_ACT))[tid] = (nn < nact) ? g_active[nn] : -1;
    }

    // patch: 264 px-rows x 16 chunks x 2 limbs
    for (int i = tid; i < 264 * 16 * 2; i += 256) {
        int limb = (i >= 264 * 16) ? 1 : 0;
        int j = i - limb * 264 * 16;
        int row = j >> 4, ch = j & 15;
        int pr = row / 66, pc = row - pr * 66;
        int gy = y0 - 1 + pr, gx = pc - 1;
        bool v = ((unsigned)gy < 64u) && ((unsigned)gx < 64u);
        const __half* base = limb ? g_Bl : g_Bh;
        const __half* src = v ? base + (((size_t)(bb << 12) + gy * 64 + gx) * 128 + ch * 8) : base;
        cp_async16(sb + (limb ? SM_PL : SM_PH) + row * PROWB + ch * 16, src, v);
    }
    // weights step 0 (k=0, chalf=0)
    for (int i = tid; i < 1024; i += 256) {
        int row = i >> 3, c16 = i & 7;
        const __half* src = g_Ah + ((size_t)(n0 + row) * 128 + c16 * 8);
        cp_async16(sb + SM_W + row * WROWB + c16 * 16, src, true);
    }
    CP_COMMIT();

    float d[4][4][4];
#pragma unroll
    for (int a = 0; a < 4; a++)
#pragma unroll
        for (int b2 = 0; b2 < 4; b2++)
#pragma unroll
            for (int c = 0; c < 4; c++) d[a][b2][c] = 0.f;

    const int pxbase = (wid & 1) << 6;
    const int nbase = (wid >> 1) << 5;
    const int rr = lane >> 2;

    for (int s = 0; s < 18; s++) {
        if (s < 17) {
            int s1 = s + 1;
            int k1 = s1 >> 1, ch1 = s1 & 1;
            for (int i = tid; i < 1024; i += 256) {
                int row = i >> 3, c16 = i & 7;
                const __half* src = g_Ah + ((size_t)(k1 * 256 + n0 + row) * 128 + ch1 * 64 + c16 * 8);
                cp_async16(sb + SM_W + (s1 & 1) * WBUF + row * WROWB + c16 * 16, src, true);
            }
            CP_COMMIT();
            CP_WAIT(1);
        } else {
            CP_WAIT(0);
        }
        __syncthreads();

        const int k = s >> 1, chalf = s & 1;
        const int dy = k / 3, dx = k - dy * 3;
        const char* WH = smem + SM_W + (s & 1) * WBUF;

        int ebase[4];
#pragma unroll
        for (int mf = 0; mf < 4; mf++) {
            int px = pxbase + mf * 16 + rr;
            ebase[mf] = (((px >> 6) + dy) * 66 + (px & 63) + dx) * PSTR;
        }
        const int coA = chalf * 64 + (lane & 3) * 2;
        const int boQ = (lane & 3) * 2;
        const int nl = rr;

#pragma unroll
        for (int cs = 0; cs < 4; cs++) {
            const int cl = cs * 16;
            uint32_t ah[4][4], al[4][4];
#pragma unroll
            for (int mf = 0; mf < 4; mf++) {
                int o = ebase[mf] + coA + cl;
                ah[mf][0] = *(const uint32_t*)(smem + SM_PH + 2 * o);
                ah[mf][1] = *(const uint32_t*)(smem + SM_PH + 2 * (o + 8 * PSTR));
                ah[mf][2] = *(const uint32_t*)(smem + SM_PH + 2 * (o + 8));
                ah[mf][3] = *(const uint32_t*)(smem + SM_PH + 2 * (o + 8 * PSTR + 8));
                al[mf][0] = *(const uint32_t*)(smem + SM_PL + 2 * o);
                al[mf][1] = *(const uint32_t*)(smem + SM_PL + 2 * (o + 8 * PSTR));
                al[mf][2] = *(const uint32_t*)(smem + SM_PL + 2 * (o + 8));
                al[mf][3] = *(const uint32_t*)(smem + SM_PL + 2 * (o + 8 * PSTR + 8));
            }
#pragma unroll
            for (int nf = 0; nf < 4; nf++) {
                int n = nbase + nf * 8 + nl;
                int bo = n * WROWB + (cl + boQ) * 2;
                uint32_t bh0 = *(const uint32_t*)(WH + bo);
                uint32_t bh1 = *(const uint32_t*)(WH + bo + 16);
#pragma unroll
                for (int mf = 0; mf < 4; mf++) {
                    MMA16816F(d[mf][nf], ah[mf], bh0, bh1);
                    MMA16816F(d[mf][nf], al[mf], bh0, bh1);
                }
            }
        }
        __syncthreads();
    }

    // epilogue
    const int* act = (const int*)(smem + SM_ACT);
#pragma unroll
    for (int mf = 0; mf < 4; mf++) {
#pragma unroll
        for (int nf = 0; nf < 4; nf++) {
            int col = nbase + nf * 8 + (lane & 3) * 2;
            int oc0 = act[col];
            int oc1 = act[col + 1];
#pragma unroll
            for (int h = 0; h < 2; h++) {
                int row = pxbase + mf * 16 + rr + h * 8;
                int y = y0 + (row >> 6);
                int x = row & 63;
                size_t pixoff = (size_t)y * 64 + x;
                if (oc0 >= 0) out[(((size_t)bb * Oc + oc0) << 12) + pixoff] = d[mf][nf][h * 2 + 0];
                if (oc1 >= 0) out[(((size_t)bb * Oc + oc1) << 12) + pixoff] = d[mf][nf][h * 2 + 1];
            }
        }
    }
}

// ---------------------------------------------------------------------------
extern "C" void kernel_launch(void* const* d_in, const int* in_sizes, int n_in,
                              void* d_out, int out_size) {
    const float* inp = (const float*)d_in[0];
    const float* kern = (const float*)d_in[1];
    const float* a = (const float*)d_in[2];
    const float* b = (const float*)d_in[3];
    float* out = (float*)d_out;

    cudaFuncSetAttribute(conv_mma_kernel, cudaFuncAttributeMaxDynamicSharedMemorySize, SM_TOT);

    hashA_kernel<<<32, 256>>>(kern, a);
    voteA_kernel<<<dim3(HW / 256, Bsz), 256>>>(inp, a);
    hashB_kernel<<<1, 256>>>(a, b);
    voteB_kernel<<<dim3(HW / 256, Bsz), 256>>>(a, b);
    argmax_mask_kernel<<<1, TBL>>>(out, (long long)out_size);
    zero_planes_kernel<<<Bsz * Oc, 256>>>(out);
    prepA_kernel<<<1152, 256>>>(kern);
    prepB_kernel<<<2048, 256>>>(inp);
    conv_mma_kernel<<<dim3(512, 2), 256, SM_TOT>>>(out);
}

// round 7
// speedup vs baseline: 4.5282x; 1.4539x over previous
#include <cuda_runtime.h>
#include <cuda_fp16.h>
#include <cstdint>

#define Bsz 16
#define Cin 128
#define Hh 64
#define Ww 64
#define HW 4096
#define Oc 256
#define ROWLEN 1152
#define ADIM 1161
#define TBL 1024
#define Rr 2.5f
#define Uu 0.83f
#define CONV_ELEMS 16777216LL

// ---------------------------------------------------------------------------
__device__ int g_bucket[Oc];
__device__ int g_count[TBL];
__device__ int g_active[Oc];
__device__ int g_maskA[Oc];
__device__ int g_nactive;
__device__ float g_dotv[Oc];
__device__ float g_nrm[Oc];
__device__ float g_T[Bsz * 9 * HW];
__device__ __half g_Ah[9 * 256 * 128];             // weights [k][m][c] fp16
__device__ __half g_Bh[(size_t)Bsz * HW * Cin];    // input NHWC fp16

// ---------------------------------------------------------------------------
__device__ __forceinline__ void cp_async16(uint32_t dst, const void* src, bool valid) {
    int sz = valid ? 16 : 0;
    asm volatile("cp.async.cg.shared.global [%0], [%1], 16, %2;" :: "r"(dst), "l"(src), "r"(sz) : "memory");
}
#define CP_COMMIT() asm volatile("cp.async.commit_group;" ::: "memory")
#define CP_WAIT(n) asm volatile("cp.async.wait_group %0;" :: "n"(n) : "memory")

__device__ __forceinline__ uint32_t smem_u32(const void* p) {
    uint32_t a;
    asm("{ .reg .u64 t; cvta.to.shared.u64 t, %1; cvt.u32.u64 %0, t; }" : "=r"(a) : "l"(p));
    return a;
}

#define MMA16816F(d, a, b0_, b1_) \
    asm volatile("mma.sync.aligned.m16n8k16.row.col.f32.f16.f16.f32 " \
        "{%0,%1,%2,%3}, {%4,%5,%6,%7}, {%8,%9}, {%0,%1,%2,%3};" \
        : "+f"((d)[0]), "+f"((d)[1]), "+f"((d)[2]), "+f"((d)[3]) \
        : "r"((a)[0]), "r"((a)[1]), "r"((a)[2]), "r"((a)[3]), "r"(b0_), "r"(b1_))

// ---------------------------------------------------------------------------
__global__ void hashA_kernel(const float* __restrict__ kern,
                             const float* __restrict__ a) {
    int tid = threadIdx.x;
    int wid = tid >> 5, lane = tid & 31;
    if (tid < 32) g_count[blockIdx.x * 32 + tid] = 0;
    int row = blockIdx.x * 8 + wid;
    const float4* kr = reinterpret_cast<const float4*>(kern + (size_t)row * ROWLEN);
    const float4* a4 = reinterpret_cast<const float4*>(a);
    float s = 0.f, d = 0.f;
    for (int j = lane; j < ROWLEN / 4; j += 32) {
        float4 kv = kr[j], av = __ldg(&a4[j]);
        s += kv.x * kv.x + kv.y * kv.y + kv.z * kv.z + kv.w * kv.w;
        d += kv.x * av.x + kv.y * av.y + kv.z * av.z + kv.w * av.w;
    }
#pragma unroll
    for (int o = 16; o > 0; o >>= 1) {
        s += __shfl_xor_sync(0xffffffff, s, o);
        d += __shfl_xor_sync(0xffffffff, d, o);
    }
    if (lane == 0) { g_dotv[row] = d; g_nrm[row] = s; }
}

__global__ void hashB_kernel(const float* __restrict__ a,
                             const float* __restrict__ bptr) {
    __shared__ float sred[256];
    __shared__ float ae[9];
    int o = threadIdx.x;
    float s = g_nrm[o];
    sred[o] = s;
    if (o < 9) ae[o] = a[ROWLEN + o];
    __syncthreads();
    for (int st = 128; st > 0; st >>= 1) {
        if (o < st) sred[o] = fmaxf(sred[o], sred[o + st]);
        __syncthreads();
    }
    float scale = Uu / sqrtf(sred[0]);
    float dot = scale * g_dotv[o];
    float p = scale * scale * s;
    float acc = 0.f, t = p;
#pragma unroll
    for (int i = 0; i < 9; i++) { acc += t * ae[i]; t = t * t; }
    int hi = (int)floorf((dot + acc + bptr[0]) / Rr);
    int bkt = hi % TBL;
    if (bkt < 0) bkt = -bkt;
    g_bucket[o] = bkt;
}

// ---------------------------------------------------------------------------
__global__ void voteA_kernel(const float* __restrict__ in, const float* __restrict__ a) {
    __shared__ __align__(16) float w_s[Cin * 12];
    int tid = threadIdx.x;
    for (int i = tid; i < ROWLEN; i += 256) { int c = i / 9, k = i % 9; w_s[c * 12 + k] = a[i]; }
    __syncthreads();
    int b = blockIdx.y;
    int p = blockIdx.x * 256 + tid;
    const float* ip = in + (size_t)b * Cin * HW + p;
    float acc[9];
#pragma unroll
    for (int k = 0; k < 9; k++) acc[k] = 0.f;
#pragma unroll 8
    for (int c = 0; c < Cin; c++) {
        float v = ip[(size_t)c * HW];
        float4 w0 = *reinterpret_cast<const float4*>(&w_s[c * 12]);
        float4 w1 = *reinterpret_cast<const float4*>(&w_s[c * 12 + 4]);
        float w8 = w_s[c * 12 + 8];
        acc[0] += v * w0.x; acc[1] += v * w0.y; acc[2] += v * w0.z; acc[3] += v * w0.w;
        acc[4] += v * w1.x; acc[5] += v * w1.y; acc[6] += v * w1.z; acc[7] += v * w1.w;
        acc[8] += v * w8;
    }
    float* tp = g_T + (size_t)b * 9 * HW + p;
#pragma unroll
    for (int k = 0; k < 9; k++) tp[k * HW] = acc[k];
}

__global__ void voteB_kernel(const float* __restrict__ a, const float* __restrict__ bptr) {
    __shared__ int hist[TBL];
    __shared__ float ae[9];
    int tid = threadIdx.x;
    for (int i = tid; i < TBL; i += 256) hist[i] = 0;
    if (tid < 9) ae[tid] = a[ROWLEN + tid];
    __syncthreads();
    int b = blockIdx.y;
    int p = blockIdx.x * 256 + tid;
    int y = p >> 6, x = p & 63;
    const float* tb = g_T + (size_t)b * 9 * HW;
    float s = 0.f;
#pragma unroll
    for (int dy = 0; dy < 3; dy++) {
        int gy = y + dy - 1;
        if (gy < 0 || gy >= Hh) continue;
#pragma unroll
        for (int dx = 0; dx < 3; dx++) {
            int gx = x + dx - 1;
            if (gx < 0 || gx >= Ww) continue;
            int k = dy * 3 + dx;
            s += tb[k * HW + gy * Ww + gx] + 0.5f * ae[k];
        }
    }
    int vi = (int)floorf((s + bptr[0]) / Rr);
    int vb = vi % TBL;
    if (vb < 0) vb = -vb;
    atomicAdd(&hist[vb], 1);
    __syncthreads();
    for (int i = tid; i < TBL; i += 256) {
        int c = hist[i];
        if (c) atomicAdd(&g_count[i], c);
    }
}

// ---------------------------------------------------------------------------
__global__ void argmax_mask_kernel(float* __restrict__ out, long long out_size) {
    __shared__ int sval[TBL];
    __shared__ int sidx[TBL];
    int t = threadIdx.x;
    sval[t] = g_count[t];
    sidx[t] = t;
    __syncthreads();
    for (int s = TBL / 2; s > 0; s >>= 1) {
        if (t < s) {
            int v2 = sval[t + s], i2 = sidx[t + s];
            if (v2 > sval[t] || (v2 == sval[t] && i2 < sidx[t])) { sval[t] = v2; sidx[t] = i2; }
        }
        __syncthreads();
    }
    int winner = sidx[0];
    if (t == 0) g_nactive = 0;
    __syncthreads();
    if (t < Oc) {
        int m = (g_bucket[t] == winner) ? 1 : 0;
        g_maskA[t] = m;
        if (m) { int pos = atomicAdd(&g_nactive, 1); g_active[pos] = t; }
        if (out_size >= CONV_ELEMS + 1 + Oc) out[CONV_ELEMS + 1 + t] = m ? 1.f : 0.f;
    }
    if (t == 0 && out_size >= CONV_ELEMS + 1) out[CONV_ELEMS] = (float)winner;
}

// ---------------------------------------------------------------------------
__global__ void zero_planes_kernel(float* __restrict__ out) {
    int plane = blockIdx.x;
    int oc = plane & 255;
    if (g_maskA[oc]) return;
    float4* p = reinterpret_cast<float4*>(out + (size_t)plane * HW);
    float4 z = make_float4(0.f, 0.f, 0.f, 0.f);
    int t = threadIdx.x;
#pragma unroll
    for (int i = 0; i < 4; i++) p[t + i * 256] = z;
}

// ---------------------------------------------------------------------------
__global__ void prepA_kernel(const float* __restrict__ kern) {
    int idx = blockIdx.x * 256 + threadIdx.x;
    int c = idx & 127;
    int m = (idx >> 7) & 255;
    int k = idx >> 15;
    int nact = g_nactive;
    float v = 0.f;
    if (m < nact) {
        int oc = g_active[m];
        v = kern[(size_t)oc * ROWLEN + c * 9 + k];
    }
    g_Ah[idx] = __float2half_rn(v);
}

// ---------------------------------------------------------------------------
__global__ void prepB_kernel(const float* __restrict__ in) {
    __shared__ float s[128 * 33];
    int tid = threadIdx.x;
    int g = blockIdx.x * 32;
    int b = g >> 12;
    int px0 = g & 4095;
    const float* ib = in + (size_t)b * Cin * HW + px0;
    for (int i = tid; i < 32 * 128; i += 256) {
        int c = i >> 5, p = i & 31;
        s[c * 33 + p] = ib[(size_t)c * HW + p];
    }
    __syncthreads();
    for (int i = tid; i < 32 * 64; i += 256) {
        int p = i >> 6, ch2 = i & 63;
        int c = ch2 * 2;
        __half h0 = __float2half_rn(s[c * 33 + p]);
        __half h1 = __float2half_rn(s[(c + 1) * 33 + p]);
        size_t o = ((size_t)(g + p) * 128 + c) >> 1;
        reinterpret_cast<__half2*>(g_Bh)[o] = __halves2half2(h0, h1);
    }
}

// ---------------------------------------------------------------------------
// Main conv: 9 shifted GEMMs, single-term fp16. CTA tile M=128px x N=128oc.
// 8 warps 2(M)x4(N); 18 double-buffered steps; 2 CTAs/SM.
// ---------------------------------------------------------------------------
#define PSTR 136
#define PROWB (PSTR * 2)
#define SM_PH 0
#define SM_W 71808
#define WBUF 18432
#define WROWB 144
#define SM_ACT 108672
#define SM_TOT 109184

__global__ void __launch_bounds__(256, 2)
conv_mma_kernel(float* __restrict__ out) {
    extern __shared__ char smem[];
    const int tid = threadIdx.x;
    const int lane = tid & 31;
    const int wid = tid >> 5;
    const int nact = g_nactive;
    const int n0 = blockIdx.y << 7;
    if (n0 >= nact) return;

    const int pxg = blockIdx.x << 7;
    const int bb = pxg >> 12;
    const int y0 = (pxg & 4095) >> 6;

    uint32_t sb = smem_u32(smem);

    if (tid < 128) {
        int nn = n0 + tid;
        ((int*)(smem + SM_ACT))[tid] = (nn < nact) ? g_active[nn] : -1;
    }

    // patch: 264 px-rows x 16 chunks
    for (int i = tid; i < 264 * 16; i += 256) {
        int row = i >> 4, ch = i & 15;
        int pr = row / 66, pc = row - pr * 66;
        int gy = y0 - 1 + pr, gx = pc - 1;
        bool v = ((unsigned)gy < 64u) && ((unsigned)gx < 64u);
        const __half* src = v ? g_Bh + (((size_t)(bb << 12) + gy * 64 + gx) * 128 + ch * 8) : g_Bh;
        cp_async16(sb + SM_PH + row * PROWB + ch * 16, src, v);
    }
    // weights step 0 (k=0, chalf=0)
    for (int i = tid; i < 1024; i += 256) {
        int row = i >> 3, c16 = i & 7;
        const __half* src = g_Ah + ((size_t)(n0 + row) * 128 + c16 * 8);
        cp_async16(sb + SM_W + row * WROWB + c16 * 16, src, true);
    }
    CP_COMMIT();

    float d[4][4][4];
#pragma unroll
    for (int a = 0; a < 4; a++)
#pragma unroll
        for (int b2 = 0; b2 < 4; b2++)
#pragma unroll
            for (int c = 0; c < 4; c++) d[a][b2][c] = 0.f;

    const int pxbase = (wid & 1) << 6;
    const int nbase = (wid >> 1) << 5;
    const int rr = lane >> 2;

    for (int s = 0; s < 18; s++) {
        if (s < 17) {
            int s1 = s + 1;
            int k1 = s1 >> 1, ch1 = s1 & 1;
            for (int i = tid; i < 1024; i += 256) {
                int row = i >> 3, c16 = i & 7;
                const __half* src = g_Ah + ((size_t)(k1 * 256 + n0 + row) * 128 + ch1 * 64 + c16 * 8);
                cp_async16(sb + SM_W + (s1 & 1) * WBUF + row * WROWB + c16 * 16, src, true);
            }
            CP_COMMIT();
            CP_WAIT(1);
        } else {
            CP_WAIT(0);
        }
        __syncthreads();

        const int k = s >> 1, chalf = s & 1;
        const int dy = k / 3, dx = k - dy * 3;
        const char* WH = smem + SM_W + (s & 1) * WBUF;

        int ebase[4];
#pragma unroll
        for (int mf = 0; mf < 4; mf++) {
            int px = pxbase + mf * 16 + rr;
            ebase[mf] = (((px >> 6) + dy) * 66 + (px & 63) + dx) * PSTR;
        }
        const int coA = chalf * 64 + (lane & 3) * 2;
        const int boQ = (lane & 3) * 2;

#pragma unroll
        for (int cs = 0; cs < 4; cs++) {
            const int cl = cs * 16;
            uint32_t ah[4][4];
#pragma unroll
            for (int mf = 0; mf < 4; mf++) {
                int o = ebase[mf] + coA + cl;
                ah[mf][0] = *(const uint32_t*)(smem + SM_PH + 2 * o);
                ah[mf][1] = *(const uint32_t*)(smem + SM_PH + 2 * (o + 8 * PSTR));
                ah[mf][2] = *(const uint32_t*)(smem + SM_PH + 2 * (o + 8));
                ah[mf][3] = *(const uint32_t*)(smem + SM_PH + 2 * (o + 8 * PSTR + 8));
            }
#pragma unroll
            for (int nf = 0; nf < 4; nf++) {
                int n = nbase + nf * 8 + rr;
                int bo = n * WROWB + (cl + boQ) * 2;
                uint32_t bh0 = *(const uint32_t*)(WH + bo);
                uint32_t bh1 = *(const uint32_t*)(WH + bo + 16);
#pragma unroll
                for (int mf = 0; mf < 4; mf++) {
                    MMA16816F(d[mf][nf], ah[mf], bh0, bh1);
                }
            }
        }
        __syncthreads();
    }

    // epilogue
    const int* act = (const int*)(smem + SM_ACT);
#pragma unroll
    for (int mf = 0; mf < 4; mf++) {
#pragma unroll
        for (int nf = 0; nf < 4; nf++) {
            int col = nbase + nf * 8 + (lane & 3) * 2;
            int oc0 = act[col];
            int oc1 = act[col + 1];
#pragma unroll
            for (int h = 0; h < 2; h++) {
                int row = pxbase + mf * 16 + rr + h * 8;
                int y = y0 + (row >> 6);
                int x = row & 63;
                size_t pixoff = (size_t)y * 64 + x;
                if (oc0 >= 0) out[(((size_t)bb * Oc + oc0) << 12) + pixoff] = d[mf][nf][h * 2 + 0];
                if (oc1 >= 0) out[(((size_t)bb * Oc + oc1) << 12) + pixoff] = d[mf][nf][h * 2 + 1];
            }
        }
    }
}

// ---------------------------------------------------------------------------
extern "C" void kernel_launch(void* const* d_in, const int* in_sizes, int n_in,
                              void* d_out, int out_size) {
    const float* inp = (const float*)d_in[0];
    const float* kern = (const float*)d_in[1];
    const float* a = (const float*)d_in[2];
    const float* b = (const float*)d_in[3];
    float* out = (float*)d_out;

    cudaFuncSetAttribute(conv_mma_kernel, cudaFuncAttributeMaxDynamicSharedMemorySize, SM_TOT);

    hashA_kernel<<<32, 256>>>(kern, a);
    voteA_kernel<<<dim3(HW / 256, Bsz), 256>>>(inp, a);
    hashB_kernel<<<1, 256>>>(a, b);
    voteB_kernel<<<dim3(HW / 256, Bsz), 256>>>(a, b);
    argmax_mask_kernel<<<1, TBL>>>(out, (long long)out_size);
    zero_planes_kernel<<<Bsz * Oc, 256>>>(out);
    prepA_kernel<<<1152, 256>>>(kern);
    prepB_kernel<<<2048, 256>>>(inp);
    conv_mma_kernel<<<dim3(512, 2), 256, SM_TOT>>>(out);
}